// round 3
// baseline (speedup 1.0000x reference)
#include <cuda_runtime.h>

#define N_TRAJ  4096
#define L_SEQ   128
#define IN_DIM  32
#define LAT     64
#define NUNITS  256
#define CDIM    160
#define TPB     256
#define ROWS    32
#define NCTA    (N_TRAJ / ROWS)   // 128 CTAs
#define CHUNK   8192              // floats per weight chunk (32KB)

// ---- shared memory float offsets ----
#define O_W    0        // 2 x 8192 weight double buffer
#define O_HT   16384    // hidden transposed [256][32] (swizzled)
#define O_CT   24576    // concat input transposed [160][32] (swizzled)
#define O_YT   29696    // state y transposed [64][32] (swizzled)
#define O_LVT  31744    // state logvar transposed [64][32] (swizzled)
#define O_YO   33792    // y_ode transposed [64][32] (swizzled)
#define O_UT   35840    // update gate [64][32] (swizzled)
#define O_XT   37888    // x transposed [32][32] (swizzled)
#define O_B    38912    // biases (1344 floats)
#define SMEM_FLOATS 40256

// bias sub-offsets within O_B
#define B_O1 0
#define B_O2 256
#define B_U1 320
#define B_U2 576
#define B_R1 640
#define B_R2 896
#define B_N1 960
#define B_N2 1216

// Swizzle: element (d, r) of a [D][32] buffer lives at
//   d*32 + (((r>>2) ^ (d&7)) << 2) + (r&3)
// i.e. 16B unit u of column d is stored at unit (u ^ (d&7)).

// ------------------------------------------------------------------
// low-level helpers
// ------------------------------------------------------------------
__device__ __forceinline__ void cp16(float* s, const float* g) {
    unsigned sa = (unsigned)__cvta_generic_to_shared(s);
    asm volatile("cp.async.cg.shared.global [%0], [%1], 16;" :: "r"(sa), "l"(g));
}
__device__ __forceinline__ void cpcommit() { asm volatile("cp.async.commit_group;"); }
template<int n> __device__ __forceinline__ void cpwait() {
    asm volatile("cp.async.wait_group %0;" :: "n"(n));
}

__device__ __forceinline__ unsigned long long pk2(float a, float b) {
    unsigned long long r;
    asm("mov.b64 %0, {%1,%2};" : "=l"(r) : "f"(a), "f"(b));
    return r;
}
__device__ __forceinline__ void upk2(unsigned long long v, float& a, float& b) {
    asm("mov.b64 {%0,%1}, %2;" : "=f"(a), "=f"(b) : "l"(v));
}
// packed 2xfp32 FMA: d = a*b + c (elementwise on the two packed lanes)
__device__ __forceinline__ unsigned long long f2fma(unsigned long long a,
                                                    unsigned long long b,
                                                    unsigned long long c) {
    unsigned long long d;
    asm("fma.rn.f32x2 %0, %1, %2, %3;" : "=l"(d) : "l"(a), "l"(b), "l"(c));
    return d;
}

__device__ __forceinline__ float sigmoidf_(float x) {
    return 1.0f / (1.0f + expf(-x));
}

// stage one 8192-float weight chunk into smem via cp.async (all 256 threads)
__device__ __forceinline__ void stage(float* s, const float* __restrict__ g, int tid) {
    #pragma unroll
    for (int i = 0; i < CHUNK / (TPB * 4); i++) {   // 8 x 16B per thread
        int off = (tid + i * TPB) * 4;
        cp16(s + off, g + off);
    }
    cpcommit();
}

// ------------------------------------------------------------------
// GEMM1: HT[256][32] = tanh( A(K x 32, transposed+swizzled)^T @ W(K x 256) + b )
// thread tid owns output column tid (all 32 rows, packed row-pairs).
// ------------------------------------------------------------------
__device__ __noinline__ void gemm1(const float* __restrict__ Wg, int K,
                                   const float* __restrict__ sA,
                                   const float* __restrict__ sbias,
                                   float* sHT, float* sW, int tid)
{
    unsigned long long acc[16];   // acc[j] = rows {2j, 2j+1}
    #pragma unroll
    for (int i = 0; i < 16; i++) acc[i] = 0ull;

    const int KC = CHUNK / NUNITS;   // 32 rows of W per chunk
    int nch = K / KC;

    stage(sW, Wg, tid);
    for (int c = 0; c < nch; c++) {
        if (c + 1 < nch) {
            stage(sW + ((c + 1) & 1) * CHUNK, Wg + (size_t)(c + 1) * CHUNK, tid);
            cpwait<1>();
        } else {
            cpwait<0>();
        }
        __syncthreads();
        const float* Wc = sW + (c & 1) * CHUNK;
        const float* Ac = sA + c * KC * ROWS;
        #pragma unroll 8
        for (int kk = 0; kk < KC; kk++) {
            float b = Wc[kk * NUNITS + tid];          // conflict-free (stride 1)
            unsigned long long b2 = pk2(b, b);
            const ulonglong2* ar = (const ulonglong2*)(Ac + kk * ROWS);  // broadcast
            int s = kk & 7;                            // == global k & 7 (KC mult of 8)
            #pragma unroll
            for (int m = 0; m < 8; m++) {
                ulonglong2 av = ar[m ^ s];             // rows 4m..4m+3
                acc[2 * m]     = f2fma(av.x, b2, acc[2 * m]);
                acc[2 * m + 1] = f2fma(av.y, b2, acc[2 * m + 1]);
            }
        }
        __syncthreads();
    }

    // epilogue: bias + tanh, 128-bit swizzled stores (4-way = crossbar optimal)
    float bias = sbias[tid];
    float4* hp = (float4*)(sHT + tid * ROWS);
    int sw = tid & 7;
    #pragma unroll
    for (int u = 0; u < 8; u++) {                      // unit u = rows 4u..4u+3
        float x0, x1, x2, x3;
        upk2(acc[2 * u],     x0, x1);
        upk2(acc[2 * u + 1], x2, x3);
        hp[u ^ sw] = make_float4(tanhf(x0 + bias), tanhf(x1 + bias),
                                 tanhf(x2 + bias), tanhf(x3 + bias));
    }
    __syncthreads();
}

// ------------------------------------------------------------------
// GEMM2: raw[32][N] = HT(256 x 32, transposed+swizzled)^T @ W(256 x N)
// thread: col c = tid & (N-1), row-group g = tid / N (N/8 rows each).
// Returns raw accumulators (caller applies bias + nonlinearity).
// ------------------------------------------------------------------
template<int N>
__device__ __forceinline__ void gemm2(const float* __restrict__ Wg,
                                      const float* __restrict__ sHT,
                                      float* sW, int tid, float* outv)
{
    const int RPT = N / 8;           // rows per thread (8 or 16)
    const int NA  = RPT / 2;         // packed accumulators
    const int UU  = RPT / 4;         // 16B A-loads per k
    const int KC  = CHUNK / N;       // W rows per chunk (128 or 64)
    const int NCH = NUNITS / KC;     // chunks (2 or 4)

    int c = tid & (N - 1);
    int g = tid / N;
    const int ub = g * UU;           // base 16B unit (rows g*RPT..)

    unsigned long long acc[NA];
    #pragma unroll
    for (int i = 0; i < NA; i++) acc[i] = 0ull;

    stage(sW, Wg, tid);
    for (int ch = 0; ch < NCH; ch++) {
        if (ch + 1 < NCH) {
            stage(sW + ((ch + 1) & 1) * CHUNK, Wg + (size_t)(ch + 1) * CHUNK, tid);
            cpwait<1>();
        } else {
            cpwait<0>();
        }
        __syncthreads();
        const float* Wc = sW + (ch & 1) * CHUNK;
        #pragma unroll 8
        for (int kk = 0; kk < KC; kk++) {
            float b = Wc[kk * N + c];                 // conflict-free
            unsigned long long b2 = pk2(b, b);
            const ulonglong2* ar =
                (const ulonglong2*)(sHT + (ch * KC + kk) * ROWS);   // broadcast
            int s = kk & 7;                            // == global k & 7
            #pragma unroll
            for (int u = 0; u < UU; u++) {
                ulonglong2 av = ar[(ub + u) ^ s];
                acc[2 * u]     = f2fma(av.x, b2, acc[2 * u]);
                acc[2 * u + 1] = f2fma(av.y, b2, acc[2 * u + 1]);
            }
        }
        __syncthreads();
    }
    #pragma unroll
    for (int i = 0; i < NA; i++) upk2(acc[i], outv[2 * i], outv[2 * i + 1]);
}

// ------------------------------------------------------------------
// persistent scan kernel: 1 CTA = 32 trajectories, full 127-step recurrence
// ------------------------------------------------------------------
__global__ void __launch_bounds__(TPB, 1)
vae_ode_rnn_kernel(const float* __restrict__ data, const float* __restrict__ ts,
                   const float* __restrict__ Wo1, const float* __restrict__ bo1,
                   const float* __restrict__ Wo2, const float* __restrict__ bo2,
                   const float* __restrict__ Wu1, const float* __restrict__ bu1,
                   const float* __restrict__ Wu2, const float* __restrict__ bu2,
                   const float* __restrict__ Wr1, const float* __restrict__ br1,
                   const float* __restrict__ Wr2, const float* __restrict__ br2,
                   const float* __restrict__ Wn1, const float* __restrict__ bn1,
                   const float* __restrict__ Wn2, const float* __restrict__ bn2,
                   float* __restrict__ out)
{
    extern __shared__ float sm[];
    float* sW   = sm + O_W;
    float* sHT  = sm + O_HT;
    float* sCT  = sm + O_CT;
    float* sYT  = sm + O_YT;
    float* sLVT = sm + O_LVT;
    float* sYO  = sm + O_YO;
    float* sUT  = sm + O_UT;
    float* sXT  = sm + O_XT;
    float* sB   = sm + O_B;

    const int tid = threadIdx.x;
    const int blk = blockIdx.x;

    // ---- one-time init: biases + zero state ----
    sB[B_O1 + tid] = bo1[tid];
    sB[B_U1 + tid] = bu1[tid];
    sB[B_R1 + tid] = br1[tid];
    sB[B_N1 + tid] = bn1[tid];
    if (tid < 64) {
        sB[B_O2 + tid] = bo2[tid];
        sB[B_U2 + tid] = bu2[tid];
        sB[B_R2 + tid] = br2[tid];
    }
    if (tid < 128) sB[B_N2 + tid] = bn2[tid];
    for (int i = tid; i < 2048; i += TPB) { sYT[i] = 0.0f; sLVT[i] = 0.0f; }
    __syncthreads();

    float a8[16];   // reused gemm2 result buffer
    for (int t = 0; t < L_SEQ - 1; t++) {
        float dt = (t == 0) ? (ts[1] - ts[0]) : (ts[t] - ts[t + 1]);

        // ---- load x for this step (data[:, t+1, :]) transposed+swizzled ----
        {
            int r = tid >> 3, kq = tid & 7;
            const float4 xv = *(const float4*)(data
                + ((size_t)(blk * ROWS + r)) * (L_SEQ * IN_DIM)
                + (size_t)(t + 1) * IN_DIM + kq * 4);
            float v[4] = {xv.x, xv.y, xv.z, xv.w};
            #pragma unroll
            for (int j = 0; j < 4; j++) {
                int d = kq * 4 + j;
                sXT[d * ROWS + (((r >> 2) ^ (d & 7)) << 2) + (r & 3)] = v[j];
            }
        }

        // ---- ODE: y_ode = y + MLP_o(y) * dt ----
        gemm1(Wo1, LAT, sYT, sB + B_O1, sHT, sW, tid);
        gemm2<LAT>(Wo2, sHT, sW, tid, a8);
        {
            int c = tid & 63, g = tid >> 6, sw = c & 7;
            float b2v = sB[B_O2 + c];
            const float4* yt = (const float4*)(sYT + c * ROWS);
            float4* yo = (float4*)(sYO + c * ROWS);
            #pragma unroll
            for (int u = 0; u < 2; u++) {              // units 2g, 2g+1
                int uu = (2 * g + u) ^ sw;
                float4 y = yt[uu];
                yo[uu] = make_float4(y.x + (a8[4 * u + 0] + b2v) * dt,
                                     y.y + (a8[4 * u + 1] + b2v) * dt,
                                     y.z + (a8[4 * u + 2] + b2v) * dt,
                                     y.w + (a8[4 * u + 3] + b2v) * dt);
            }
        }
        __syncthreads();

        // ---- build yc = [y_ode ; logvar ; x] (all identically swizzled) ----
        for (int i = tid * 4; i < 2048; i += TPB * 4)
            *(float4*)(sCT + i) = *(const float4*)(sYO + i);
        for (int i = tid * 4; i < 2048; i += TPB * 4)
            *(float4*)(sCT + 2048 + i) = *(const float4*)(sLVT + i);
        if (tid * 4 < 1024)
            *(float4*)(sCT + 4096 + tid * 4) = *(const float4*)(sXT + tid * 4);

        // ---- update gate -> sUT ----
        gemm1(Wu1, CDIM, sCT, sB + B_U1, sHT, sW, tid);
        gemm2<LAT>(Wu2, sHT, sW, tid, a8);
        {
            int c = tid & 63, g = tid >> 6, sw = c & 7;
            float b2v = sB[B_U2 + c];
            float4* ut = (float4*)(sUT + c * ROWS);
            #pragma unroll
            for (int u = 0; u < 2; u++) {
                int uu = (2 * g + u) ^ sw;
                ut[uu] = make_float4(sigmoidf_(a8[4 * u + 0] + b2v),
                                     sigmoidf_(a8[4 * u + 1] + b2v),
                                     sigmoidf_(a8[4 * u + 2] + b2v),
                                     sigmoidf_(a8[4 * u + 3] + b2v));
            }
        }

        // ---- reset gate: fold directly into cc = [y_ode*r ; logvar*r ; x] ----
        gemm1(Wr1, CDIM, sCT, sB + B_R1, sHT, sW, tid);
        gemm2<LAT>(Wr2, sHT, sW, tid, a8);
        __syncthreads();   // everyone done reading sCT before we overwrite it
        {
            int c = tid & 63, g = tid >> 6, sw = c & 7;
            float b2v = sB[B_R2 + c];
            const float4* yo = (const float4*)(sYO + c * ROWS);
            const float4* lv = (const float4*)(sLVT + c * ROWS);
            float4* cy = (float4*)(sCT + c * ROWS);
            float4* cl = (float4*)(sCT + 2048 + c * ROWS);
            #pragma unroll
            for (int u = 0; u < 2; u++) {
                int uu = (2 * g + u) ^ sw;
                float4 rr = make_float4(sigmoidf_(a8[4 * u + 0] + b2v),
                                        sigmoidf_(a8[4 * u + 1] + b2v),
                                        sigmoidf_(a8[4 * u + 2] + b2v),
                                        sigmoidf_(a8[4 * u + 3] + b2v));
                float4 y = yo[uu], l = lv[uu];
                cy[uu] = make_float4(y.x * rr.x, y.y * rr.y, y.z * rr.z, y.w * rr.w);
                cl[uu] = make_float4(l.x * rr.x, l.y * rr.y, l.z * rr.z, l.w * rr.w);
            }
        }
        __syncthreads();

        // ---- candidate: h = MLP_n(cc), then gated blend into state ----
        gemm1(Wn1, CDIM, sCT, sB + B_N1, sHT, sW, tid);
        gemm2<128>(Wn2, sHT, sW, tid, a8);
        {
            int c = tid & 127, g = tid >> 7;
            float b2v = sB[B_N2 + c];
            if (c < LAT) {
                int sw = c & 7;
                const float4* ut = (const float4*)(sUT + c * ROWS);
                const float4* yo = (const float4*)(sYO + c * ROWS);
                float4* yt = (float4*)(sYT + c * ROWS);
                #pragma unroll
                for (int u = 0; u < 4; u++) {          // units 4g..4g+3
                    int uu = (4 * g + u) ^ sw;
                    float4 uv = ut[uu], yv = yo[uu];
                    float h0 = a8[4 * u + 0] + b2v, h1 = a8[4 * u + 1] + b2v;
                    float h2 = a8[4 * u + 2] + b2v, h3 = a8[4 * u + 3] + b2v;
                    yt[uu] = make_float4((1.0f - uv.x) * h0 + uv.x * yv.x,
                                         (1.0f - uv.y) * h1 + uv.y * yv.y,
                                         (1.0f - uv.z) * h2 + uv.z * yv.z,
                                         (1.0f - uv.w) * h3 + uv.w * yv.w);
                }
            } else {
                int cl = c - LAT, sw = cl & 7;
                const float4* ut = (const float4*)(sUT + cl * ROWS);
                float4* lt = (float4*)(sLVT + cl * ROWS);
                #pragma unroll
                for (int u = 0; u < 4; u++) {
                    int uu = (4 * g + u) ^ sw;
                    float4 uv = ut[uu], lv = lt[uu];
                    float s0 = fabsf(a8[4 * u + 0] + b2v), s1 = fabsf(a8[4 * u + 1] + b2v);
                    float s2 = fabsf(a8[4 * u + 2] + b2v), s3 = fabsf(a8[4 * u + 3] + b2v);
                    lt[uu] = make_float4((1.0f - uv.x) * s0 + uv.x * lv.x,
                                         (1.0f - uv.y) * s1 + uv.y * lv.y,
                                         (1.0f - uv.z) * s2 + uv.z * lv.z,
                                         (1.0f - uv.w) * s3 + uv.w * lv.w);
                }
            }
        }
        __syncthreads();
    }

    // ---- write outputs: [yi (4096x64) ; yi_logvar (4096x64)] ----
    for (int i = tid; i < 2048; i += TPB) {
        int r = i >> 6, c = i & 63;
        int sa = c * ROWS + (((r >> 2) ^ (c & 7)) << 2) + (r & 3);
        size_t gofs = ((size_t)(blk * ROWS + r)) * LAT + c;
        out[gofs] = sYT[sa];
        out[(size_t)N_TRAJ * LAT + gofs] = sLVT[sa];
    }
}

// ------------------------------------------------------------------
extern "C" void kernel_launch(void* const* d_in, const int* in_sizes, int n_in,
                              void* d_out, int out_size)
{
    (void)in_sizes; (void)n_in; (void)out_size;
    cudaFuncSetAttribute(vae_ode_rnn_kernel,
                         cudaFuncAttributeMaxDynamicSharedMemorySize,
                         SMEM_FLOATS * sizeof(float));
    vae_ode_rnn_kernel<<<NCTA, TPB, SMEM_FLOATS * sizeof(float)>>>(
        (const float*)d_in[0],  (const float*)d_in[1],
        (const float*)d_in[2],  (const float*)d_in[3],
        (const float*)d_in[4],  (const float*)d_in[5],
        (const float*)d_in[6],  (const float*)d_in[7],
        (const float*)d_in[8],  (const float*)d_in[9],
        (const float*)d_in[10], (const float*)d_in[11],
        (const float*)d_in[12], (const float*)d_in[13],
        (const float*)d_in[14], (const float*)d_in[15],
        (const float*)d_in[16], (const float*)d_in[17],
        (float*)d_out);
}

// round 5
// speedup vs baseline: 1.1121x; 1.1121x over previous
#include <cuda_runtime.h>

#define N_TRAJ  4096
#define L_SEQ   128
#define IN_DIM  32
#define LAT     64
#define NUNITS  256
#define CDIM    160
#define TPB     512
#define ROWS    32
#define NCTA    (N_TRAJ / ROWS)   // 128 CTAs
#define CHUNK   8192              // floats per weight chunk (32KB)

// ---- shared memory float offsets ----
#define O_W    0        // 2 x 8192 weight double buffer
#define O_HT   16384    // hidden transposed [256][32] (swizzled)
#define O_CT   24576    // concat input transposed [160][32] (swizzled)
#define O_YT   29696    // state y transposed [64][32] (swizzled)
#define O_LVT  31744    // state logvar transposed [64][32] (swizzled)
#define O_YO   33792    // y_ode transposed [64][32] (swizzled)
#define O_UT   35840    // update gate [64][32] (swizzled)
#define O_XT   37888    // x transposed [32][32] (swizzled)
#define O_B    38912    // biases (1344 floats)
#define O_DT   40256    // dts (128 floats)
#define SMEM_FLOATS 40384

// bias sub-offsets within O_B
#define B_O1 0
#define B_O2 256
#define B_U1 320
#define B_U2 576
#define B_R1 640
#define B_R2 896
#define B_N1 960
#define B_N2 1216

// Swizzle: element (d, r) of a [D][32] buffer lives at
//   d*32 + (((r>>2) ^ (d&7)) << 2) + (r&3)
// i.e. 16B unit u of column d is stored at unit (u ^ (d&7)).

// ------------------------------------------------------------------
// low-level helpers
// ------------------------------------------------------------------
__device__ __forceinline__ void cp16(float* s, const float* g) {
    unsigned sa = (unsigned)__cvta_generic_to_shared(s);
    asm volatile("cp.async.cg.shared.global [%0], [%1], 16;" :: "r"(sa), "l"(g));
}
__device__ __forceinline__ void cpcommit() { asm volatile("cp.async.commit_group;"); }
template<int n> __device__ __forceinline__ void cpwait() {
    asm volatile("cp.async.wait_group %0;" :: "n"(n));
}

__device__ __forceinline__ unsigned long long pk2(float a, float b) {
    unsigned long long r;
    asm("mov.b64 %0, {%1,%2};" : "=l"(r) : "f"(a), "f"(b));
    return r;
}
__device__ __forceinline__ void upk2(unsigned long long v, float& a, float& b) {
    asm("mov.b64 {%0,%1}, %2;" : "=f"(a), "=f"(b) : "l"(v));
}
// packed 2xfp32 FMA: d = a*b + c (elementwise on the two packed lanes)
__device__ __forceinline__ unsigned long long f2fma(unsigned long long a,
                                                    unsigned long long b,
                                                    unsigned long long c) {
    unsigned long long d;
    asm("fma.rn.f32x2 %0, %1, %2, %3;" : "=l"(d) : "l"(a), "l"(b), "l"(c));
    return d;
}

// MUFU-based fast transcendentals (rel err ~1e-6, far under tolerance)
__device__ __forceinline__ float ftanh(float x) {
    float e = __expf(2.0f * x);
    return 1.0f - __fdividef(2.0f, e + 1.0f);
}
__device__ __forceinline__ float fsig(float x) {
    return __fdividef(1.0f, 1.0f + __expf(-x));
}

// stage one 8192-float weight chunk into smem via cp.async (all 512 threads)
__device__ __forceinline__ void stage(float* s, const float* __restrict__ g, int tid) {
    #pragma unroll
    for (int i = 0; i < CHUNK / (TPB * 4); i++) {   // 4 x 16B per thread
        int off = (tid + i * TPB) * 4;
        cp16(s + off, g + off);
    }
    cpcommit();
}

// ------------------------------------------------------------------
// GEMM1: HT[256][32] = tanh( A(K x 32, transposed+swizzled)^T @ W(K x 256) + b )
// thread: cols {c, c+128} (c = tid&127), rows 8g..8g+7 (g = tid>>7).
// ------------------------------------------------------------------
__device__ __noinline__ void gemm1(const float* __restrict__ Wg, int K,
                                   const float* __restrict__ sA,
                                   const float* __restrict__ sbias,
                                   float* sHT, float* sW, int tid)
{
    const int c = tid & 127;
    const int g = tid >> 7;          // 0..3 -> units 2g, 2g+1
    unsigned long long acc[8];       // [col0 pairs 0..3][col1 pairs 0..3]
    #pragma unroll
    for (int i = 0; i < 8; i++) acc[i] = 0ull;

    const int KC = CHUNK / NUNITS;   // 32 rows of W per chunk
    int nch = K / KC;

    stage(sW, Wg, tid);
    for (int ch = 0; ch < nch; ch++) {
        if (ch + 1 < nch) {
            stage(sW + ((ch + 1) & 1) * CHUNK, Wg + (size_t)(ch + 1) * CHUNK, tid);
            cpwait<1>();
        } else {
            cpwait<0>();
        }
        __syncthreads();
        const float* Wc = sW + (ch & 1) * CHUNK;
        const float* Ac = sA + ch * KC * ROWS;
        #pragma unroll 8
        for (int kk = 0; kk < KC; kk++) {
            float b0 = Wc[kk * NUNITS + c];           // conflict-free scalar
            float b1 = Wc[kk * NUNITS + c + 128];     // conflict-free scalar
            unsigned long long B0 = pk2(b0, b0);
            unsigned long long B1 = pk2(b1, b1);
            const ulonglong2* ar = (const ulonglong2*)(Ac + kk * ROWS);  // broadcast
            int s = kk & 7;                            // == global k & 7
            ulonglong2 a0 = ar[(2 * g) ^ s];           // rows 8g..8g+3
            ulonglong2 a1 = ar[(2 * g + 1) ^ s];       // rows 8g+4..8g+7
            acc[0] = f2fma(a0.x, B0, acc[0]);
            acc[1] = f2fma(a0.y, B0, acc[1]);
            acc[2] = f2fma(a1.x, B0, acc[2]);
            acc[3] = f2fma(a1.y, B0, acc[3]);
            acc[4] = f2fma(a0.x, B1, acc[4]);
            acc[5] = f2fma(a0.y, B1, acc[5]);
            acc[6] = f2fma(a1.x, B1, acc[6]);
            acc[7] = f2fma(a1.y, B1, acc[7]);
        }
        __syncthreads();
    }

    // epilogue: bias + tanh, 128-bit swizzled stores (4-way = crossbar optimal)
    #pragma unroll
    for (int p = 0; p < 2; p++) {
        int col = c + p * 128;
        float bias = sbias[col];
        int swc = col & 7;
        float4* hp = (float4*)(sHT + col * ROWS);
        float x0, x1, x2, x3;
        upk2(acc[4 * p + 0], x0, x1);
        upk2(acc[4 * p + 1], x2, x3);
        hp[(2 * g) ^ swc] = make_float4(ftanh(x0 + bias), ftanh(x1 + bias),
                                        ftanh(x2 + bias), ftanh(x3 + bias));
        upk2(acc[4 * p + 2], x0, x1);
        upk2(acc[4 * p + 3], x2, x3);
        hp[(2 * g + 1) ^ swc] = make_float4(ftanh(x0 + bias), ftanh(x1 + bias),
                                            ftanh(x2 + bias), ftanh(x3 + bias));
    }
    __syncthreads();
}

// ------------------------------------------------------------------
// GEMM2: raw[32][N] = HT(256 x 32, transposed+swizzled)^T @ W(256 x N)
// thread: col c = tid & (N-1), row-group g = tid / N (RPT = 32N/512 rows each).
// ------------------------------------------------------------------
template<int N>
__device__ __forceinline__ void gemm2(const float* __restrict__ Wg,
                                      const float* __restrict__ sHT,
                                      float* sW, int tid, float* outv)
{
    const int RPT = (ROWS * N) / TPB;  // 4 (N=64) or 8 (N=128)
    const int NA  = RPT / 2;           // packed accumulators
    const int UU  = RPT / 4;           // 16B A-loads per k
    const int KC  = CHUNK / N;         // W rows per chunk (128 or 64)
    const int NCH = NUNITS / KC;       // chunks (2 or 4)

    int c = tid & (N - 1);
    int g = tid / N;
    const int ub = g * UU;             // base 16B unit

    unsigned long long acc[NA];
    #pragma unroll
    for (int i = 0; i < NA; i++) acc[i] = 0ull;

    stage(sW, Wg, tid);
    for (int ch = 0; ch < NCH; ch++) {
        if (ch + 1 < NCH) {
            stage(sW + ((ch + 1) & 1) * CHUNK, Wg + (size_t)(ch + 1) * CHUNK, tid);
            cpwait<1>();
        } else {
            cpwait<0>();
        }
        __syncthreads();
        const float* Wc = sW + (ch & 1) * CHUNK;
        #pragma unroll 8
        for (int kk = 0; kk < KC; kk++) {
            float b = Wc[kk * N + c];                 // conflict-free
            unsigned long long b2 = pk2(b, b);
            const ulonglong2* ar =
                (const ulonglong2*)(sHT + (ch * KC + kk) * ROWS);   // broadcast
            int s = kk & 7;
            #pragma unroll
            for (int u = 0; u < UU; u++) {
                ulonglong2 av = ar[(ub + u) ^ s];
                acc[2 * u]     = f2fma(av.x, b2, acc[2 * u]);
                acc[2 * u + 1] = f2fma(av.y, b2, acc[2 * u + 1]);
            }
        }
        __syncthreads();
    }
    #pragma unroll
    for (int i = 0; i < NA; i++) upk2(acc[i], outv[2 * i], outv[2 * i + 1]);
}

// ------------------------------------------------------------------
// persistent scan kernel: 1 CTA = 32 trajectories, full 127-step recurrence
// ------------------------------------------------------------------
__global__ void __launch_bounds__(TPB, 1)
vae_ode_rnn_kernel(const float* __restrict__ data, const float* __restrict__ ts,
                   const float* __restrict__ Wo1, const float* __restrict__ bo1,
                   const float* __restrict__ Wo2, const float* __restrict__ bo2,
                   const float* __restrict__ Wu1, const float* __restrict__ bu1,
                   const float* __restrict__ Wu2, const float* __restrict__ bu2,
                   const float* __restrict__ Wr1, const float* __restrict__ br1,
                   const float* __restrict__ Wr2, const float* __restrict__ br2,
                   const float* __restrict__ Wn1, const float* __restrict__ bn1,
                   const float* __restrict__ Wn2, const float* __restrict__ bn2,
                   float* __restrict__ out)
{
    extern __shared__ float sm[];
    float* sW   = sm + O_W;
    float* sHT  = sm + O_HT;
    float* sCT  = sm + O_CT;
    float* sYT  = sm + O_YT;
    float* sLVT = sm + O_LVT;
    float* sYO  = sm + O_YO;
    float* sUT  = sm + O_UT;
    float* sXT  = sm + O_XT;
    float* sB   = sm + O_B;
    float* sDT  = sm + O_DT;

    const int tid = threadIdx.x;
    const int blk = blockIdx.x;

    // ---- one-time init: biases + dts + zero state ----
    if (tid < 256) {
        sB[B_O1 + tid] = bo1[tid];
        sB[B_U1 + tid] = bu1[tid];
        sB[B_R1 + tid] = br1[tid];
        sB[B_N1 + tid] = bn1[tid];
        if (tid < 64) {
            sB[B_O2 + tid] = bo2[tid];
            sB[B_U2 + tid] = bu2[tid];
            sB[B_R2 + tid] = br2[tid];
        }
        if (tid < 128) sB[B_N2 + tid] = bn2[tid];
    }
    if (tid < L_SEQ - 1)
        sDT[tid] = (tid == 0) ? (ts[1] - ts[0]) : (ts[tid] - ts[tid + 1]);
    for (int i = tid; i < 2048; i += TPB) { sYT[i] = 0.0f; sLVT[i] = 0.0f; }
    __syncthreads();

    float a8[8];   // reused gemm2 result buffer
    for (int t = 0; t < L_SEQ - 1; t++) {
        float dt = sDT[t];

        // ---- load x for this step (data[:, t+1, :]) transposed+swizzled ----
        if (tid < 256) {
            int r = tid >> 3, kq = tid & 7;
            const float4 xv = *(const float4*)(data
                + ((size_t)(blk * ROWS + r)) * (L_SEQ * IN_DIM)
                + (size_t)(t + 1) * IN_DIM + kq * 4);
            float v[4] = {xv.x, xv.y, xv.z, xv.w};
            #pragma unroll
            for (int j = 0; j < 4; j++) {
                int d = kq * 4 + j;
                sXT[d * ROWS + (((r >> 2) ^ (d & 7)) << 2) + (r & 3)] = v[j];
            }
        }

        // ---- ODE: y_ode = y + MLP_o(y) * dt ----
        gemm1(Wo1, LAT, sYT, sB + B_O1, sHT, sW, tid);
        gemm2<LAT>(Wo2, sHT, sW, tid, a8);
        {
            int c = tid & 63, g = tid >> 6, sw = c & 7;   // unit g (rows 4g..4g+3)
            float b2v = sB[B_O2 + c];
            int uu = g ^ sw;
            const float4* yt = (const float4*)(sYT + c * ROWS);
            float4* yo = (float4*)(sYO + c * ROWS);
            float4 y = yt[uu];
            yo[uu] = make_float4(y.x + (a8[0] + b2v) * dt,
                                 y.y + (a8[1] + b2v) * dt,
                                 y.z + (a8[2] + b2v) * dt,
                                 y.w + (a8[3] + b2v) * dt);
        }
        __syncthreads();

        // ---- build yc = [y_ode ; logvar ; x] (all identically swizzled) ----
        // 512 threads: each copies float4 tid of y_ode AND float4 tid of logvar.
        *(float4*)(sCT + tid * 4)        = *(const float4*)(sYO  + tid * 4);
        *(float4*)(sCT + 2048 + tid * 4) = *(const float4*)(sLVT + tid * 4);
        if (tid < 256)
            *(float4*)(sCT + 4096 + tid * 4) = *(const float4*)(sXT + tid * 4);

        // ---- update gate -> sUT ----
        gemm1(Wu1, CDIM, sCT, sB + B_U1, sHT, sW, tid);
        gemm2<LAT>(Wu2, sHT, sW, tid, a8);
        {
            int c = tid & 63, g = tid >> 6, sw = c & 7;
            float b2v = sB[B_U2 + c];
            int uu = g ^ sw;
            float4* ut = (float4*)(sUT + c * ROWS);
            ut[uu] = make_float4(fsig(a8[0] + b2v), fsig(a8[1] + b2v),
                                 fsig(a8[2] + b2v), fsig(a8[3] + b2v));
        }

        // ---- reset gate: fold directly into cc = [y_ode*r ; logvar*r ; x] ----
        gemm1(Wr1, CDIM, sCT, sB + B_R1, sHT, sW, tid);
        gemm2<LAT>(Wr2, sHT, sW, tid, a8);
        __syncthreads();   // everyone done reading sCT before overwrite
        {
            int c = tid & 63, g = tid >> 6, sw = c & 7;
            float b2v = sB[B_R2 + c];
            int uu = g ^ sw;
            const float4* yo = (const float4*)(sYO + c * ROWS);
            const float4* lv = (const float4*)(sLVT + c * ROWS);
            float4* cy = (float4*)(sCT + c * ROWS);
            float4* cl = (float4*)(sCT + 2048 + c * ROWS);
            float4 rr = make_float4(fsig(a8[0] + b2v), fsig(a8[1] + b2v),
                                    fsig(a8[2] + b2v), fsig(a8[3] + b2v));
            float4 y = yo[uu], l = lv[uu];
            cy[uu] = make_float4(y.x * rr.x, y.y * rr.y, y.z * rr.z, y.w * rr.w);
            cl[uu] = make_float4(l.x * rr.x, l.y * rr.y, l.z * rr.z, l.w * rr.w);
        }
        __syncthreads();

        // ---- candidate: h = MLP_n(cc), then gated blend into state ----
        gemm1(Wn1, CDIM, sCT, sB + B_N1, sHT, sW, tid);
        gemm2<128>(Wn2, sHT, sW, tid, a8);
        {
            int c = tid & 127, g = tid >> 7;   // rows 8g..8g+7, units 2g, 2g+1
            float b2v = sB[B_N2 + c];
            if (c < LAT) {
                int sw = c & 7;
                const float4* ut = (const float4*)(sUT + c * ROWS);
                const float4* yo = (const float4*)(sYO + c * ROWS);
                float4* yt = (float4*)(sYT + c * ROWS);
                #pragma unroll
                for (int u = 0; u < 2; u++) {
                    int uu = (2 * g + u) ^ sw;
                    float4 uv = ut[uu], yv = yo[uu];
                    float h0 = a8[4 * u + 0] + b2v, h1 = a8[4 * u + 1] + b2v;
                    float h2 = a8[4 * u + 2] + b2v, h3 = a8[4 * u + 3] + b2v;
                    yt[uu] = make_float4((1.0f - uv.x) * h0 + uv.x * yv.x,
                                         (1.0f - uv.y) * h1 + uv.y * yv.y,
                                         (1.0f - uv.z) * h2 + uv.z * yv.z,
                                         (1.0f - uv.w) * h3 + uv.w * yv.w);
                }
            } else {
                int cl = c - LAT, sw = cl & 7;
                const float4* ut = (const float4*)(sUT + cl * ROWS);
                float4* lt = (float4*)(sLVT + cl * ROWS);
                #pragma unroll
                for (int u = 0; u < 2; u++) {
                    int uu = (2 * g + u) ^ sw;
                    float4 uv = ut[uu], lv = lt[uu];
                    float s0 = fabsf(a8[4 * u + 0] + b2v), s1 = fabsf(a8[4 * u + 1] + b2v);
                    float s2 = fabsf(a8[4 * u + 2] + b2v), s3 = fabsf(a8[4 * u + 3] + b2v);
                    lt[uu] = make_float4((1.0f - uv.x) * s0 + uv.x * lv.x,
                                         (1.0f - uv.y) * s1 + uv.y * lv.y,
                                         (1.0f - uv.z) * s2 + uv.z * lv.z,
                                         (1.0f - uv.w) * s3 + uv.w * lv.w);
                }
            }
        }
        __syncthreads();
    }

    // ---- write outputs: [yi (4096x64) ; yi_logvar (4096x64)] ----
    for (int i = tid; i < 2048; i += TPB) {
        int r = i >> 6, c = i & 63;
        int sa = c * ROWS + (((r >> 2) ^ (c & 7)) << 2) + (r & 3);
        size_t gofs = ((size_t)(blk * ROWS + r)) * LAT + c;
        out[gofs] = sYT[sa];
        out[(size_t)N_TRAJ * LAT + gofs] = sLVT[sa];
    }
}

// ------------------------------------------------------------------
extern "C" void kernel_launch(void* const* d_in, const int* in_sizes, int n_in,
                              void* d_out, int out_size)
{
    (void)in_sizes; (void)n_in; (void)out_size;
    cudaFuncSetAttribute(vae_ode_rnn_kernel,
                         cudaFuncAttributeMaxDynamicSharedMemorySize,
                         SMEM_FLOATS * sizeof(float));
    vae_ode_rnn_kernel<<<NCTA, TPB, SMEM_FLOATS * sizeof(float)>>>(
        (const float*)d_in[0],  (const float*)d_in[1],
        (const float*)d_in[2],  (const float*)d_in[3],
        (const float*)d_in[4],  (const float*)d_in[5],
        (const float*)d_in[6],  (const float*)d_in[7],
        (const float*)d_in[8],  (const float*)d_in[9],
        (const float*)d_in[10], (const float*)d_in[11],
        (const float*)d_in[12], (const float*)d_in[13],
        (const float*)d_in[14], (const float*)d_in[15],
        (const float*)d_in[16], (const float*)d_in[17],
        (float*)d_out);
}